// round 1
// baseline (speedup 1.0000x reference)
#include <cuda_runtime.h>
#include <cuda_bf16.h>
#include <cstdint>

// Problem constants
#define NN   12288
#define KK   32
#define DD   128

// Scratch: G = raw_features @ W_lin^T   (N x 128 fp32, 6.3 MB)
__device__ float g_G[NN * DD];

// ---------------------------------------------------------------------------
// Kernel 1: G[m][n] = sum_k F[m][k] * W[n][k]
// 96 blocks x 256 threads, 128x128 output tile per block, 8x8 register microtile.
// Both operands staged in smem with pad-129 rows.
//   thread -> (tx = tid&15, ty = tid>>4); m = ty + 16*i, n = tx + 16*j
//   B-reads: Ws[(tx+16j)*129 + kk] -> stride 129 words across tx => 16 distinct
//            banks (129 % 32 == 1) => conflict-free.
//   A-reads: 2 distinct ty per warp => broadcast.
// ---------------------------------------------------------------------------
__global__ void __launch_bounds__(256, 1)
gemm_G_kernel(const float* __restrict__ F, const float* __restrict__ W)
{
    extern __shared__ float sm[];
    float* Fs = sm;               // 128 * 129
    float* Ws = sm + 128 * 129;   // 128 * 129

    const int tid = threadIdx.x;
    const int bm  = blockIdx.x;

    const float* Fblk = F + (size_t)bm * 128 * DD;

    // Stage tiles (coalesced LDG, stride-1 STS => conflict-free)
    #pragma unroll 8
    for (int idx = tid; idx < 128 * 128; idx += 256) {
        int r = idx >> 7, c = idx & 127;
        Fs[r * 129 + c] = Fblk[idx];
        Ws[r * 129 + c] = W[idx];
    }
    __syncthreads();

    const int tx = tid & 15;
    const int ty = tid >> 4;

    float acc[8][8];
    #pragma unroll
    for (int i = 0; i < 8; i++)
        #pragma unroll
        for (int j = 0; j < 8; j++)
            acc[i][j] = 0.0f;

    #pragma unroll 4
    for (int kk = 0; kk < 128; kk++) {
        float a[8], b[8];
        #pragma unroll
        for (int i = 0; i < 8; i++) a[i] = Fs[(ty + 16 * i) * 129 + kk];
        #pragma unroll
        for (int j = 0; j < 8; j++) b[j] = Ws[(tx + 16 * j) * 129 + kk];
        #pragma unroll
        for (int i = 0; i < 8; i++)
            #pragma unroll
            for (int j = 0; j < 8; j++)
                acc[i][j] = fmaf(a[i], b[j], acc[i][j]);
    }

    float* Gout = g_G + (size_t)bm * 128 * DD;
    #pragma unroll
    for (int i = 0; i < 8; i++) {
        int m = ty + 16 * i;
        #pragma unroll
        for (int j = 0; j < 8; j++) {
            int n = tx + 16 * j;
            Gout[m * DD + n] = acc[i][j];
        }
    }
}

// ---------------------------------------------------------------------------
// Kernel 2: out[b][d] = relu( sum_k w[b][k] * G[nb[b][k]][d] + bias[d] )
//   w[b][k] = (nb==node) ? 0 : reweighted[node*N + nb],  node = nodes[b]
// 4 nodes per block, 512 threads (128 threads = one node, one column each).
// ---------------------------------------------------------------------------
__global__ void __launch_bounds__(512, 4)
gather_kernel(const int* __restrict__ nodes,
              const int* __restrict__ neighbors,
              const float* __restrict__ rew,
              const float* __restrict__ b_lin,
              float* __restrict__ out)
{
    __shared__ int   nb_s[4][KK];
    __shared__ float w_s [4][KK];

    const int tid = threadIdx.x;
    const int b0  = blockIdx.x * 4;

    if (tid < 4 * KK) {
        const int ln = tid >> 5;       // local node 0..3
        const int k  = tid & 31;
        const int b  = b0 + ln;
        const int node = nodes[b];
        const int nb   = neighbors[b * KK + k];
        float w = 0.0f;
        if (nb != node)
            w = __ldg(&rew[(size_t)node * NN + nb]);
        nb_s[ln][k] = nb;
        w_s [ln][k] = w;
    }
    __syncthreads();

    const int ln = tid >> 7;           // local node 0..3 (constant per warp)
    const int d  = tid & 127;          // feature column
    const int b  = b0 + ln;

    float acc = 0.0f;
    #pragma unroll
    for (int k = 0; k < KK; k++) {
        const int   nb = nb_s[ln][k];
        const float w  = w_s[ln][k];
        acc = fmaf(w, g_G[(size_t)nb * DD + d], acc);
    }

    out[(size_t)b * DD + d] = fmaxf(acc + __ldg(&b_lin[d]), 0.0f);
}

// ---------------------------------------------------------------------------
// Launch
// Inputs (metadata order): nodes(i32 N), neighbors(i32 N*K), raw_features(f32 N*128),
//                          reweighted(f32 N*N), W_lin(f32 128*128), b_lin(f32 128)
// ---------------------------------------------------------------------------
extern "C" void kernel_launch(void* const* d_in, const int* in_sizes, int n_in,
                              void* d_out, int out_size)
{
    const int*   nodes     = (const int*)  d_in[0];
    const int*   neighbors = (const int*)  d_in[1];
    const float* raw_feats = (const float*)d_in[2];
    const float* reweighted= (const float*)d_in[3];
    const float* W_lin     = (const float*)d_in[4];
    const float* b_lin     = (const float*)d_in[5];
    float*       out       = (float*)d_out;

    const int smem = 2 * 128 * 129 * (int)sizeof(float);  // 132096 B
    static bool attr_set = false;
    if (!attr_set) {
        cudaFuncSetAttribute(gemm_G_kernel,
                             cudaFuncAttributeMaxDynamicSharedMemorySize, smem);
        attr_set = true;
    }

    gemm_G_kernel<<<NN / 128, 256, smem>>>(raw_feats, W_lin);
    gather_kernel<<<NN / 4, 512>>>(nodes, neighbors, reweighted, b_lin, out);
}

// round 2
// speedup vs baseline: 1.1906x; 1.1906x over previous
#include <cuda_runtime.h>
#include <cuda_bf16.h>
#include <cstdint>

#define NN   12288
#define KK   32
#define DD   128

// Scratch: G = raw_features @ W_lin^T   (N x 128 fp32, 6.3 MB)
__device__ __align__(16) float g_G[NN * DD];

// ---------------------------------------------------------------------------
// packed f32x2 helpers (sm_103a: FFMA2 only reachable via PTX fma.rn.f32x2)
// ---------------------------------------------------------------------------
__device__ __forceinline__ unsigned long long pack_dup(float x) {
    unsigned long long r;
    asm("mov.b64 %0, {%1, %1};" : "=l"(r) : "f"(x));
    return r;
}
__device__ __forceinline__ void fma2(unsigned long long& d,
                                     unsigned long long a,
                                     unsigned long long b) {
    asm("fma.rn.f32x2 %0, %1, %2, %0;" : "+l"(d) : "l"(a), "l"(b));
}

// ---------------------------------------------------------------------------
// Kernel 1: G[m][n] = sum_k F[m][k] * W[n][k]
// 192 blocks x 256 threads, 64x128 tile, FFMA2 microtile 8 rows x 2 col-pairs.
//   Fs: 64 x (pad 129)  — a-reads are warp-broadcast (ty uniform per warp)
//   Wt: transposed W, k-major rows of 128 cols, pad 130 (even => LDS.64 aligned;
//       staging banks (2k+n)%32 => worst 2-way; inner reads contiguous 256B)
// ---------------------------------------------------------------------------
__global__ void __launch_bounds__(256, 2)
gemm_G_kernel(const float* __restrict__ F, const float* __restrict__ W)
{
    extern __shared__ float sm[];
    float* Fs = sm;                 // 64 * 129
    float* Wt = sm + 64 * 129;      // 128 * 130  (Wt[k*130 + n] = W[n][k])

    const int tid = threadIdx.x;
    const int bm  = blockIdx.x;
    const float* Fblk = F + (size_t)bm * 64 * DD;

    // Stage F tile (coalesced, stride-1 => conflict-free)
    #pragma unroll 4
    for (int idx = tid; idx < 64 * 128; idx += 256) {
        int r = idx >> 7, c = idx & 127;
        Fs[r * 129 + c] = Fblk[idx];
    }
    // Stage W transposed
    #pragma unroll 8
    for (int idx = tid; idx < 128 * 128; idx += 256) {
        int n = idx >> 7, k = idx & 127;
        Wt[k * 130 + n] = W[idx];
    }
    __syncthreads();

    const int tx = tid & 31;   // pair-column slot (cols 2*(tx+32j))
    const int ty = tid >> 5;   // row slot (rows ty + 8i), uniform per warp

    unsigned long long acc[8][2];
    #pragma unroll
    for (int i = 0; i < 8; i++) { acc[i][0] = 0ULL; acc[i][1] = 0ULL; }

    #pragma unroll 4
    for (int kk = 0; kk < 128; kk++) {
        unsigned long long b2[2];
        #pragma unroll
        for (int j = 0; j < 2; j++)
            b2[j] = *reinterpret_cast<const unsigned long long*>(
                        &Wt[kk * 130 + 2 * (tx + 32 * j)]);
        #pragma unroll
        for (int i = 0; i < 8; i++) {
            unsigned long long a2 = pack_dup(Fs[(ty + 8 * i) * 129 + kk]);
            fma2(acc[i][0], a2, b2[0]);
            fma2(acc[i][1], a2, b2[1]);
        }
    }

    float* Gout = g_G + (size_t)bm * 64 * DD;
    #pragma unroll
    for (int i = 0; i < 8; i++) {
        int m = ty + 8 * i;
        #pragma unroll
        for (int j = 0; j < 2; j++) {
            int n = 2 * (tx + 32 * j);
            *reinterpret_cast<unsigned long long*>(&Gout[m * DD + n]) = acc[i][j];
        }
    }
}

// ---------------------------------------------------------------------------
// Kernel 2: out[b][d] = relu( sum_k w[b][k] * G[nb[b][k]][d] + bias[d] )
// One warp per node; lane l owns columns 4l..4l+3 (float4).
// (nb, w) live in registers (lane k holds k-th pair), broadcast via shfl.
// ---------------------------------------------------------------------------
__global__ void __launch_bounds__(256)
gather_kernel(const int* __restrict__ nodes,
              const int* __restrict__ neighbors,
              const float* __restrict__ rew,
              const float* __restrict__ b_lin,
              float* __restrict__ out)
{
    const int lane = threadIdx.x & 31;
    const int wrp  = threadIdx.x >> 5;
    const int b    = blockIdx.x * 8 + wrp;

    const int node = nodes[b];                       // broadcast load
    const int nb_l = neighbors[b * KK + lane];       // coalesced
    float w_l = 0.0f;
    if (nb_l != node)
        w_l = __ldg(&rew[(size_t)node * NN + nb_l]); // scattered 32B sectors

    float4 acc = make_float4(0.f, 0.f, 0.f, 0.f);

    #pragma unroll
    for (int k = 0; k < KK; k++) {
        const int   nbk = __shfl_sync(0xffffffffu, nb_l, k);
        const float wk  = __shfl_sync(0xffffffffu, w_l,  k);
        const float4 g = __ldg(reinterpret_cast<const float4*>(
                                   &g_G[(size_t)nbk * DD + lane * 4]));
        acc.x = fmaf(wk, g.x, acc.x);
        acc.y = fmaf(wk, g.y, acc.y);
        acc.z = fmaf(wk, g.z, acc.z);
        acc.w = fmaf(wk, g.w, acc.w);
    }

    const float4 bias = __ldg(reinterpret_cast<const float4*>(&b_lin[lane * 4]));
    float4 o;
    o.x = fmaxf(acc.x + bias.x, 0.f);
    o.y = fmaxf(acc.y + bias.y, 0.f);
    o.z = fmaxf(acc.z + bias.z, 0.f);
    o.w = fmaxf(acc.w + bias.w, 0.f);
    *reinterpret_cast<float4*>(&out[(size_t)b * DD + lane * 4]) = o;
}

// ---------------------------------------------------------------------------
// Launch. Inputs: nodes(i32 N), neighbors(i32 N*K), raw_features(f32 N*128),
//                 reweighted(f32 N*N), W_lin(f32 128*128), b_lin(f32 128)
// ---------------------------------------------------------------------------
extern "C" void kernel_launch(void* const* d_in, const int* in_sizes, int n_in,
                              void* d_out, int out_size)
{
    const int*   nodes      = (const int*)  d_in[0];
    const int*   neighbors  = (const int*)  d_in[1];
    const float* raw_feats  = (const float*)d_in[2];
    const float* reweighted = (const float*)d_in[3];
    const float* W_lin      = (const float*)d_in[4];
    const float* b_lin      = (const float*)d_in[5];
    float*       out        = (float*)d_out;

    const int smem = (64 * 129 + 128 * 130) * (int)sizeof(float);  // 99584 B
    static bool attr_set = false;
    if (!attr_set) {
        cudaFuncSetAttribute(gemm_G_kernel,
                             cudaFuncAttributeMaxDynamicSharedMemorySize, smem);
        attr_set = true;
    }

    gemm_G_kernel<<<NN / 64, 256, smem>>>(raw_feats, W_lin);
    gather_kernel<<<NN / 8, 256>>>(nodes, neighbors, reweighted, b_lin, out);
}